// round 1
// baseline (speedup 1.0000x reference)
#include <cuda_runtime.h>
#include <cuda_bf16.h>
#include <cstdint>

#define N_TOK 8192
#define DIM   2048
#define HID   8192
#define KSEL  4096

// ---------------- scratch (device globals; no allocation allowed) -----------
__device__ __nv_bfloat16 g_w1b[(size_t)DIM * HID];   // 32MB
__device__ __nv_bfloat16 g_w2b[(size_t)HID * DIM];   // 32MB
__device__ __nv_bfloat16 g_xn [(size_t)N_TOK * DIM]; // 32MB  x_norm (bf16)
__device__ __nv_bfloat16 g_h  [(size_t)KSEL * HID];  // 64MB  gelu(h)
__device__ float    g_logits[N_TOK];
__device__ int      g_sel[KSEL];
__device__ unsigned g_thr_key;
__device__ int      g_cnt_greater;
__device__ int      g_c_gt, g_c_tie;

// ---------------- helpers ---------------------------------------------------
__device__ __forceinline__ float gelu_exact(float v) {
    return 0.5f * v * (1.0f + erff(v * 0.70710678118654752f));
}
__device__ __forceinline__ unsigned float_key(float f) {
    unsigned u = __float_as_uint(f);
    return (u & 0x80000000u) ? ~u : (u | 0x80000000u);
}
__device__ __forceinline__ uint32_t pack_bf2(float a, float b) {
    return (uint32_t)__bfloat16_as_ushort(__float2bfloat16_rn(a)) |
           ((uint32_t)__bfloat16_as_ushort(__float2bfloat16_rn(b)) << 16);
}

// ---------------- weight fp32 -> bf16 ---------------------------------------
__global__ void conv_kernel(const float4* __restrict__ src, int which) {
    int i = blockIdx.x * blockDim.x + threadIdx.x;
    const int n4 = DIM * HID / 4;
    if (i >= n4) return;
    float4 v = src[i];
    uint2 o;
    o.x = pack_bf2(v.x, v.y);
    o.y = pack_bf2(v.z, v.w);
    uint2* dst = which ? reinterpret_cast<uint2*>(g_w2b) : reinterpret_cast<uint2*>(g_w1b);
    dst[i] = o;
}

// ---------------- RMSNorm + router logit + x passthrough ---------------------
__device__ __forceinline__ float block_reduce_sum256(float v, float* red) {
    __syncthreads();
    int lane = threadIdx.x & 31, warp = threadIdx.x >> 5;
    #pragma unroll
    for (int o = 16; o > 0; o >>= 1) v += __shfl_xor_sync(0xffffffffu, v, o);
    if (lane == 0) red[warp] = v;
    __syncthreads();
    if (threadIdx.x == 0) {
        float s = 0.f;
        #pragma unroll
        for (int i = 0; i < 8; i++) s += red[i];
        red[8] = s;
    }
    __syncthreads();
    return red[8];
}

__global__ __launch_bounds__(256) void rmsnorm_router_kernel(
    const float* __restrict__ x, const float* __restrict__ nw,
    const float* __restrict__ rw, float* __restrict__ out)
{
    __shared__ float red[9];
    int row = blockIdx.x;
    int tid = threadIdx.x;
    const float4* x4 = reinterpret_cast<const float4*>(x + (size_t)row * DIM);
    float4 v0 = x4[tid];
    float4 v1 = x4[tid + 256];
    float ss = v0.x*v0.x + v0.y*v0.y + v0.z*v0.z + v0.w*v0.w +
               v1.x*v1.x + v1.y*v1.y + v1.z*v1.z + v1.w*v1.w;
    float tot = block_reduce_sum256(ss, red);
    float rms = rsqrtf(tot * (1.0f / DIM) + 1e-6f);

    float4* o4 = reinterpret_cast<float4*>(out + (size_t)row * DIM);
    uint2* xn2 = reinterpret_cast<uint2*>(g_xn + (size_t)row * DIM);
    float logit = 0.f;

    {   // chunk 0: cols [tid*4, tid*4+3]
        int c = tid * 4;
        float n0 = v0.x * rms * nw[c+0];
        float n1 = v0.y * rms * nw[c+1];
        float n2 = v0.z * rms * nw[c+2];
        float n3 = v0.w * rms * nw[c+3];
        logit += n0*rw[c+0] + n1*rw[c+1] + n2*rw[c+2] + n3*rw[c+3];
        uint2 p; p.x = pack_bf2(n0, n1); p.y = pack_bf2(n2, n3);
        xn2[tid] = p;
        o4[tid] = v0;
    }
    {   // chunk 1
        int c = (tid + 256) * 4;
        float n0 = v1.x * rms * nw[c+0];
        float n1 = v1.y * rms * nw[c+1];
        float n2 = v1.z * rms * nw[c+2];
        float n3 = v1.w * rms * nw[c+3];
        logit += n0*rw[c+0] + n1*rw[c+1] + n2*rw[c+2] + n3*rw[c+3];
        uint2 p; p.x = pack_bf2(n0, n1); p.y = pack_bf2(n2, n3);
        xn2[tid + 256] = p;
        o4[tid + 256] = v1;
    }
    float lt = block_reduce_sum256(logit, red);
    if (tid == 0) g_logits[row] = lt;   // sigmoid is monotonic -> skip
}

// ---------------- exact k-th largest via 4-pass radix select -----------------
__global__ __launch_bounds__(256) void topk_select_kernel() {
    __shared__ unsigned skey[N_TOK];
    __shared__ int hist[256];
    __shared__ int s_krem, s_bin, s_cnt;
    int tid = threadIdx.x;
    for (int i = tid; i < N_TOK; i += 256) skey[i] = float_key(g_logits[i]);
    if (tid == 0) s_krem = KSEL;
    __syncthreads();

    unsigned prefix = 0, mask = 0;
    for (int shift = 24; shift >= 0; shift -= 8) {
        hist[tid & 255] = 0;
        __syncthreads();
        for (int i = tid; i < N_TOK; i += 256) {
            unsigned u = skey[i];
            if ((u & mask) == prefix) atomicAdd(&hist[(u >> shift) & 255], 1);
        }
        __syncthreads();
        if (tid == 0) {
            int krem = s_krem, cum = 0, b = 0;
            for (int j = 255; j >= 0; --j) {
                if (cum + hist[j] >= krem) { b = j; break; }
                cum += hist[j];
            }
            s_krem = krem - cum;
            s_bin = b;
        }
        __syncthreads();
        prefix |= ((unsigned)s_bin) << shift;
        mask   |= 0xFFu << shift;
        __syncthreads();
    }
    if (tid == 0) s_cnt = 0;
    __syncthreads();
    int c = 0;
    for (int i = tid; i < N_TOK; i += 256) if (skey[i] > prefix) c++;
    atomicAdd(&s_cnt, c);
    __syncthreads();
    if (tid == 0) {
        g_thr_key = prefix;
        g_cnt_greater = s_cnt;
        g_c_gt = 0; g_c_tie = 0;
    }
}

__global__ void compact_kernel() {
    int i = blockIdx.x * blockDim.x + threadIdx.x;
    if (i >= N_TOK) return;
    unsigned u = float_key(g_logits[i]);
    unsigned thr = g_thr_key;
    if (u > thr) {
        int p = atomicAdd(&g_c_gt, 1);
        g_sel[p] = i;
    } else if (u == thr) {
        int t = atomicAdd(&g_c_tie, 1);
        int need = KSEL - g_cnt_greater;
        if (t < need) g_sel[g_cnt_greater + t] = i;
    }
}

// ---------------- bf16 mma.sync GEMM (128x128x32, 8 warps, cp.async) ---------
#define BM 128
#define BN 128
#define BK 32
#define SA_LD 40
#define SB_LD 136

__device__ __forceinline__ void cp16(uint32_t s, const void* g) {
    asm volatile("cp.async.cg.shared.global [%0], [%1], 16;" :: "r"(s), "l"(g));
}
__device__ __forceinline__ void cp_commit() { asm volatile("cp.async.commit_group;"); }
__device__ __forceinline__ void cp_wait0()  { asm volatile("cp.async.wait_group 0;"); }

__device__ __forceinline__ void ldmx4(uint32_t& r0, uint32_t& r1, uint32_t& r2, uint32_t& r3, uint32_t a) {
    asm volatile("ldmatrix.sync.aligned.m8n8.x4.shared.b16 {%0,%1,%2,%3}, [%4];"
                 : "=r"(r0), "=r"(r1), "=r"(r2), "=r"(r3) : "r"(a));
}
__device__ __forceinline__ void ldmx4t(uint32_t& r0, uint32_t& r1, uint32_t& r2, uint32_t& r3, uint32_t a) {
    asm volatile("ldmatrix.sync.aligned.m8n8.x4.trans.shared.b16 {%0,%1,%2,%3}, [%4];"
                 : "=r"(r0), "=r"(r1), "=r"(r2), "=r"(r3) : "r"(a));
}
__device__ __forceinline__ void mma16816(float* c, const uint32_t* a, uint32_t b0, uint32_t b1) {
    asm volatile("mma.sync.aligned.m16n8k16.row.col.f32.bf16.bf16.f32 "
                 "{%0,%1,%2,%3},{%4,%5,%6,%7},{%8,%9},{%0,%1,%2,%3};"
                 : "+f"(c[0]), "+f"(c[1]), "+f"(c[2]), "+f"(c[3])
                 : "r"(a[0]), "r"(a[1]), "r"(a[2]), "r"(a[3]), "r"(b0), "r"(b1));
}

// EPI==0: A = g_xn gathered by g_sel, B = g_w1b, out = g_h (gelu+bias, bf16)
// EPI==1: A = g_h,                   B = g_w2b, out = x + gamma*(acc+b2) scattered
template<int EPI, int Kdim, int Ncols>
__global__ __launch_bounds__(256, 2) void gemm_kernel(
    const float* __restrict__ bias,
    const float* __restrict__ x,
    const float* __restrict__ gamma,
    float* __restrict__ out)
{
    const __nv_bfloat16* __restrict__ A = (EPI == 0) ? g_xn : g_h;
    const __nv_bfloat16* __restrict__ B = (EPI == 0) ? g_w1b : g_w2b;
    __shared__ alignas(16) __nv_bfloat16 sA[2][BM * SA_LD];
    __shared__ alignas(16) __nv_bfloat16 sB[2][BK * SB_LD];

    const int tid = threadIdx.x;
    const int bm = blockIdx.y, bn = blockIdx.x;

    // A tile loads: 2 x 16B per thread (rows tid/4 and tid/4+64, 8 bf16 cols)
    const int ar0 = tid >> 2;
    const int ac  = (tid & 3) << 3;
    const int ar1 = ar0 + 64;
    size_t grow0, grow1;
    if (EPI == 0) { grow0 = (size_t)g_sel[bm * BM + ar0]; grow1 = (size_t)g_sel[bm * BM + ar1]; }
    else          { grow0 = (size_t)(bm * BM + ar0);       grow1 = (size_t)(bm * BM + ar1); }
    const __nv_bfloat16* aptr0 = A + grow0 * Kdim + ac;
    const __nv_bfloat16* aptr1 = A + grow1 * Kdim + ac;

    // B tile loads: 2 x 16B per thread (rows tid/16 and +16, 8 bf16 cols)
    const int br0 = tid >> 4;
    const int bc  = (tid & 15) << 3;
    const int br1 = br0 + 16;
    const __nv_bfloat16* bptr0 = B + (size_t)br0 * Ncols + (size_t)bn * BN + bc;
    const __nv_bfloat16* bptr1 = B + (size_t)br1 * Ncols + (size_t)bn * BN + bc;

    const uint32_t sA_u = (uint32_t)__cvta_generic_to_shared(&sA[0][0]);
    const uint32_t sB_u = (uint32_t)__cvta_generic_to_shared(&sB[0][0]);
    const uint32_t sAstage = BM * SA_LD * 2;
    const uint32_t sBstage = BK * SB_LD * 2;
    const uint32_t sa_dst0 = sA_u + (ar0 * SA_LD + ac) * 2;
    const uint32_t sa_dst1 = sA_u + (ar1 * SA_LD + ac) * 2;
    const uint32_t sb_dst0 = sB_u + (br0 * SB_LD + bc) * 2;
    const uint32_t sb_dst1 = sB_u + (br1 * SB_LD + bc) * 2;

    float acc[2][8][4];
    #pragma unroll
    for (int i = 0; i < 2; i++)
        #pragma unroll
        for (int j = 0; j < 8; j++)
            #pragma unroll
            for (int q = 0; q < 4; q++) acc[i][j][q] = 0.f;

    const int lane = tid & 31;
    const int warp = tid >> 5;
    const int wm = (warp & 3) * 32;
    const int wn = (warp >> 2) * 64;
    const int lrow = lane & 15;
    const int lcol = (lane >> 4) << 3;

    // prologue loads
    {
        cp16(sa_dst0, aptr0);
        cp16(sa_dst1, aptr1);
        cp16(sb_dst0, bptr0);
        cp16(sb_dst1, bptr1);
        cp_commit();
    }

    const int KT = Kdim / BK;
    for (int kt = 0; kt < KT; ++kt) {
        const int s = kt & 1;
        cp_wait0();
        __syncthreads();
        if (kt + 1 < KT) {
            const int k0 = (kt + 1) * BK;
            const int so = (s ^ 1);
            cp16(sa_dst0 + so * sAstage, aptr0 + k0);
            cp16(sa_dst1 + so * sAstage, aptr1 + k0);
            cp16(sb_dst0 + so * sBstage, bptr0 + (size_t)k0 * Ncols);
            cp16(sb_dst1 + so * sBstage, bptr1 + (size_t)k0 * Ncols);
            cp_commit();
        }
        const uint32_t aBase = sA_u + s * sAstage;
        const uint32_t bBase = sB_u + s * sBstage;
        #pragma unroll
        for (int ks = 0; ks < 2; ++ks) {
            uint32_t af[2][4];
            #pragma unroll
            for (int mi = 0; mi < 2; ++mi) {
                uint32_t addr = aBase + (((wm + mi * 16 + lrow) * SA_LD) + ks * 16 + lcol) * 2;
                ldmx4(af[mi][0], af[mi][1], af[mi][2], af[mi][3], addr);
            }
            #pragma unroll
            for (int ni = 0; ni < 4; ++ni) {
                uint32_t bf0, bf1, bf2, bf3;
                uint32_t addr = bBase + (((ks * 16 + lrow) * SB_LD) + wn + ni * 16 + lcol) * 2;
                ldmx4t(bf0, bf1, bf2, bf3, addr);
                #pragma unroll
                for (int mi = 0; mi < 2; ++mi) {
                    mma16816(acc[mi][2 * ni],     af[mi], bf0, bf1);
                    mma16816(acc[mi][2 * ni + 1], af[mi], bf2, bf3);
                }
            }
        }
        __syncthreads();
    }

    // -------- epilogue --------
    const int r  = lane >> 2;
    const int cc = (lane & 3) << 1;
    if (EPI == 0) {
        #pragma unroll
        for (int mi = 0; mi < 2; ++mi) {
            const int gm0 = bm * BM + wm + mi * 16 + r;
            #pragma unroll
            for (int nj = 0; nj < 8; ++nj) {
                const int gn = bn * BN + wn + nj * 8 + cc;
                const float b0 = bias[gn], b1v = bias[gn + 1];
                float v0 = gelu_exact(acc[mi][nj][0] + b0);
                float v1 = gelu_exact(acc[mi][nj][1] + b1v);
                float v2 = gelu_exact(acc[mi][nj][2] + b0);
                float v3 = gelu_exact(acc[mi][nj][3] + b1v);
                *reinterpret_cast<uint32_t*>(&g_h[(size_t)gm0 * Ncols + gn])       = pack_bf2(v0, v1);
                *reinterpret_cast<uint32_t*>(&g_h[(size_t)(gm0 + 8) * Ncols + gn]) = pack_bf2(v2, v3);
            }
        }
    } else {
        #pragma unroll
        for (int mi = 0; mi < 2; ++mi) {
            const int m0 = bm * BM + wm + mi * 16 + r;
            const int tok0 = g_sel[m0];
            const int tok1 = g_sel[m0 + 8];
            #pragma unroll
            for (int nj = 0; nj < 8; ++nj) {
                const int gn = bn * BN + wn + nj * 8 + cc;
                const float bb0 = bias[gn], bb1 = bias[gn + 1];
                const float gg0 = gamma[gn], gg1 = gamma[gn + 1];
                const float* xr0 = x + (size_t)tok0 * Ncols + gn;
                const float* xr1 = x + (size_t)tok1 * Ncols + gn;
                float2 o0, o1;
                o0.x = xr0[0] + gg0 * (acc[mi][nj][0] + bb0);
                o0.y = xr0[1] + gg1 * (acc[mi][nj][1] + bb1);
                o1.x = xr1[0] + gg0 * (acc[mi][nj][2] + bb0);
                o1.y = xr1[1] + gg1 * (acc[mi][nj][3] + bb1);
                *reinterpret_cast<float2*>(out + (size_t)tok0 * Ncols + gn) = o0;
                *reinterpret_cast<float2*>(out + (size_t)tok1 * Ncols + gn) = o1;
            }
        }
    }
}

// ---------------- launch -----------------------------------------------------
extern "C" void kernel_launch(void* const* d_in, const int* in_sizes, int n_in,
                              void* d_out, int out_size) {
    const float* x     = (const float*)d_in[0];
    const float* nw    = (const float*)d_in[1];
    const float* rw    = (const float*)d_in[2];
    const float* w1    = (const float*)d_in[4];
    const float* b1    = (const float*)d_in[5];
    const float* w2    = (const float*)d_in[6];
    const float* b2    = (const float*)d_in[7];
    const float* gamma = (const float*)d_in[8];
    float* out = (float*)d_out;

    const int n4 = DIM * HID / 4;
    conv_kernel<<<(n4 + 255) / 256, 256>>>((const float4*)w1, 0);
    conv_kernel<<<(n4 + 255) / 256, 256>>>((const float4*)w2, 1);
    rmsnorm_router_kernel<<<N_TOK, 256>>>(x, nw, rw, out);
    topk_select_kernel<<<1, 256>>>();
    compact_kernel<<<N_TOK / 256, 256>>>();
    gemm_kernel<0, DIM, HID><<<dim3(HID / BN, KSEL / BM), 256>>>(b1, nullptr, nullptr, nullptr);
    gemm_kernel<1, HID, DIM><<<dim3(DIM / BN, KSEL / BM), 256>>>(b2, x, gamma, out);
}